// round 6
// baseline (speedup 1.0000x reference)
#include <cuda_runtime.h>

// ---------------------------------------------------------------------------
// OTRouter: logits GEMM -> 20-iter Sinkhorn (log domain) -> pi, top-8, KL loss
//
// Shapes: x (8,8192,2048) f32, gate_w (64,2048) f32
// N_TOK = 65536 tokens, NE = 64 experts, KD = 2048
// Output f32 buffer layout: [dispatch 65536*64 | indices 65536*8 | load_loss]
// ---------------------------------------------------------------------------

#define N_TOK   65536
#define NE      64
#define KD      2048
#define N_IT    20
#define INV_EPS 20.0f          // 1 / 0.05

#define DISP_ELEMS (N_TOK * NE)          // 4194304
#define IDX_OFF    DISP_ELEMS
#define IDX_ELEMS  (N_TOK * 8)           // 524288
#define LOSS_OFF   (IDX_OFF + IDX_ELEMS) // 4718592

#define GRID_A  296                      // 2 * 148 SMs
#define BLOCK_A 512
#define NWARP_A (BLOCK_A / 32)           // 16
#define TOTWARP (GRID_A * NWARP_A)       // 4736

// ---- persistent device scratch (no allocations allowed) -------------------
__device__ float g_state[(size_t)N_TOK * NE];   // logits, then row-normed la
__device__ float g_colLog[NE];                  // column logsumexp of exp(state)
__device__ float g_partials[GRID_A * NE];       // per-block column partial sums
__device__ int   g_counter;                     // last-block ticket (self-resetting)

// ---- packed f32x2 helpers (sm_103a FFMA2) ---------------------------------
__device__ __forceinline__ unsigned long long fma2(unsigned long long a,
                                                   unsigned long long b,
                                                   unsigned long long c) {
    unsigned long long d;
    asm("fma.rn.f32x2 %0, %1, %2, %3;" : "=l"(d) : "l"(a), "l"(b), "l"(c));
    return d;
}
__device__ __forceinline__ unsigned long long pack2(float a) {
    unsigned long long d; unsigned int u = __float_as_uint(a);
    asm("mov.b64 %0, {%1, %1};" : "=l"(d) : "r"(u));
    return d;
}
__device__ __forceinline__ float2 unpack2(unsigned long long v) {
    unsigned int lo, hi;
    asm("mov.b64 {%0, %1}, %2;" : "=r"(lo), "=r"(hi) : "l"(v));
    return make_float2(__uint_as_float(lo), __uint_as_float(hi));
}

// ---------------------------------------------------------------------------
// GEMM: g_state[n][e] = sum_k x[n][k] * w[e][k]   (fp32, packed f32x2 FMA)
// Block: 128 tokens x 64 experts, 128 threads, thread tile 8x8.
// ---------------------------------------------------------------------------
__global__ void __launch_bounds__(128) gemm_kernel(const float* __restrict__ x,
                                                   const float* __restrict__ w)
{
    __shared__ __align__(16) float xs[32][132];  // [k][m], padded
    __shared__ __align__(16) float ws[32][68];   // [k][e], padded (rows 16B-aligned)

    const int tid = threadIdx.x;
    const int tx = tid & 7;          // expert-group (8 experts)
    const int ty = tid >> 3;         // row-group    (8 rows)
    const int rowBase = blockIdx.x * 128;

    unsigned long long acc[8][4];
#pragma unroll
    for (int r = 0; r < 8; ++r)
#pragma unroll
        for (int c = 0; c < 4; ++c) acc[r][c] = 0ULL;

    for (int k0 = 0; k0 < KD; k0 += 32) {
        // stage x tile (128 rows x 32 k), transposed into xs[k][m]
#pragma unroll
        for (int i = 0; i < 8; ++i) {
            int q  = tid + i * 128;
            int m  = q >> 3, c4 = q & 7;
            float4 f = *(const float4*)(x + (size_t)(rowBase + m) * KD + k0 + c4 * 4);
            xs[c4 * 4 + 0][m] = f.x; xs[c4 * 4 + 1][m] = f.y;
            xs[c4 * 4 + 2][m] = f.z; xs[c4 * 4 + 3][m] = f.w;
        }
        // stage w tile (64 experts x 32 k), transposed into ws[k][e]
#pragma unroll
        for (int i = 0; i < 4; ++i) {
            int q  = tid + i * 128;
            int e  = q >> 3, c4 = q & 7;
            float4 f = *(const float4*)(w + (size_t)e * KD + k0 + c4 * 4);
            ws[c4 * 4 + 0][e] = f.x; ws[c4 * 4 + 1][e] = f.y;
            ws[c4 * 4 + 2][e] = f.z; ws[c4 * 4 + 3][e] = f.w;
        }
        __syncthreads();

#pragma unroll
        for (int kk = 0; kk < 32; ++kk) {
            float4 a0 = *(const float4*)&xs[kk][ty * 8];
            float4 a1 = *(const float4*)&xs[kk][ty * 8 + 4];
            ulonglong2 wA = *(const ulonglong2*)&ws[kk][tx * 8];      // (e0,e1),(e2,e3)
            ulonglong2 wB = *(const ulonglong2*)&ws[kk][tx * 8 + 4];  // (e4,e5),(e6,e7)
            float av[8] = {a0.x, a0.y, a0.z, a0.w, a1.x, a1.y, a1.z, a1.w};
#pragma unroll
            for (int r = 0; r < 8; ++r) {
                unsigned long long ap = pack2(av[r]);
                acc[r][0] = fma2(ap, wA.x, acc[r][0]);
                acc[r][1] = fma2(ap, wA.y, acc[r][1]);
                acc[r][2] = fma2(ap, wB.x, acc[r][2]);
                acc[r][3] = fma2(ap, wB.y, acc[r][3]);
            }
        }
        __syncthreads();
    }

#pragma unroll
    for (int r = 0; r < 8; ++r) {
        int gr = rowBase + ty * 8 + r;
        float2 p0 = unpack2(acc[r][0]);
        float2 p1 = unpack2(acc[r][1]);
        float2 p2 = unpack2(acc[r][2]);
        float2 p3 = unpack2(acc[r][3]);
        float* dst = g_state + (size_t)gr * NE + tx * 8;
        *(float4*)dst       = make_float4(p0.x, p0.y, p1.x, p1.y);
        *(float4*)(dst + 4) = make_float4(p2.x, p2.y, p3.x, p3.y);
    }
}

// ---------------------------------------------------------------------------
// One Sinkhorn iteration.
//  state_in (iter>0): row-normed la of previous iter (col norm deferred)
//  la        = state*scale - colLog                  (scale=-20 on iter 0)
//  state_out = la - rowLSE(la)
//  colLog    = log( sum_n exp(state_out[n][e]) )     (last-block reduction)
// Warp handles one token: lane l owns experts 2l, 2l+1.
// ---------------------------------------------------------------------------
__global__ void __launch_bounds__(BLOCK_A) sinkhorn_step(int iter)
{
    __shared__ __align__(16) float part[NWARP_A][NE];
    __shared__ bool isLast;

    const int tid  = threadIdx.x;
    const int lane = tid & 31;
    const int wrp  = tid >> 5;
    const int e0   = 2 * lane;

    float scale, cl0, cl1;
    if (iter == 0) { scale = -INV_EPS; cl0 = 0.f; cl1 = 0.f; }
    else           { scale = 1.0f; cl0 = g_colLog[e0]; cl1 = g_colLog[e0 + 1]; }

    float acc0 = 0.f, acc1 = 0.f;
    const int warpGlobal = blockIdx.x * NWARP_A + wrp;

    for (int n = warpGlobal; n < N_TOK; n += TOTWARP) {
        float2 v = *(const float2*)(g_state + (size_t)n * NE + e0);
        float v0 = v.x * scale - cl0;
        float v1 = v.y * scale - cl1;

        float m = fmaxf(v0, v1);
#pragma unroll
        for (int off = 16; off; off >>= 1)
            m = fmaxf(m, __shfl_xor_sync(0xffffffffu, m, off));

        float t0 = __expf(v0 - m);
        float t1 = __expf(v1 - m);
        float s = t0 + t1;
#pragma unroll
        for (int off = 16; off; off >>= 1)
            s += __shfl_xor_sync(0xffffffffu, s, off);

        float lse = m + __logf(s);
        *(float2*)(g_state + (size_t)n * NE + e0) = make_float2(v0 - lse, v1 - lse);

        float inv = 1.0f / s;                 // exp(v - lse) = t * inv
        acc0 += t0 * inv;
        acc1 += t1 * inv;
    }

    // block-level column partials
    *(float2*)&part[wrp][e0] = make_float2(acc0, acc1);
    __syncthreads();
    if (tid < NE) {
        float s = 0.f;
#pragma unroll
        for (int ww = 0; ww < NWARP_A; ++ww) s += part[ww][tid];
        g_partials[blockIdx.x * NE + tid] = s;
    }
    __threadfence();
    __syncthreads();
    if (tid == 0) isLast = (atomicAdd(&g_counter, 1) == GRID_A - 1);
    __syncthreads();
    if (!isLast) return;

    // last block: reduce GRID_A partials -> colLog
    __threadfence();
    const int e  = tid & 63;
    const int sl = tid >> 6;                  // 0..7, each sums 37 blocks
    float s = 0.f;
    for (int j = 0; j < GRID_A / 8; ++j)
        s += g_partials[(sl * (GRID_A / 8) + j) * NE + e];
    __syncthreads();
    part[sl][e] = s;
    __syncthreads();
    if (tid < NE) {
        float tot = 0.f;
#pragma unroll
        for (int q = 0; q < 8; ++q) tot += part[q][tid];
        g_colLog[tid] = __logf(tot);
    }
    if (tid == 0) g_counter = 0;              // reset for next launch / replay
}

// ---------------------------------------------------------------------------
// Finalize: pi = exp(state - colLog); write dispatch, top-8 indices (as f32),
// accumulate column sums of pi; last block computes the KL load loss.
// ---------------------------------------------------------------------------
__global__ void __launch_bounds__(BLOCK_A) finalize_kernel(float* __restrict__ out)
{
    __shared__ __align__(16) float part[NWARP_A][NE];
    __shared__ bool isLast;

    const int tid  = threadIdx.x;
    const int lane = tid & 31;
    const int wrp  = tid >> 5;
    const int e0   = 2 * lane;
    const int e1   = e0 + 1;

    const float cl0 = g_colLog[e0];
    const float cl1 = g_colLog[e1];

    float acc0 = 0.f, acc1 = 0.f;
    const int warpGlobal = blockIdx.x * NWARP_A + wrp;

    for (int n = warpGlobal; n < N_TOK; n += TOTWARP) {
        float2 v = *(const float2*)(g_state + (size_t)n * NE + e0);
        float p0 = __expf(v.x - cl0);
        float p1 = __expf(v.y - cl1);
        *(float2*)(out + (size_t)n * NE + e0) = make_float2(p0, p1);
        acc0 += p0;
        acc1 += p1;

        // top-8 by value, ties -> lower index (jax.lax.top_k semantics)
        float v0 = p0, v1 = p1;
#pragma unroll
        for (int r = 0; r < 8; ++r) {
            float bv; int bi;
            if (v0 >= v1) { bv = v0; bi = e0; } else { bv = v1; bi = e1; }
#pragma unroll
            for (int off = 16; off; off >>= 1) {
                float ov = __shfl_xor_sync(0xffffffffu, bv, off);
                int   oi = __shfl_xor_sync(0xffffffffu, bi, off);
                if (ov > bv || (ov == bv && oi < bi)) { bv = ov; bi = oi; }
            }
            if (lane == 0) out[IDX_OFF + (size_t)n * 8 + r] = (float)bi;
            if (bi == e0) v0 = -1.0f;
            else if (bi == e1) v1 = -1.0f;
        }
    }

    // column sums of pi (for load_loss)
    *(float2*)&part[wrp][e0] = make_float2(acc0, acc1);
    __syncthreads();
    if (tid < NE) {
        float s = 0.f;
#pragma unroll
        for (int ww = 0; ww < NWARP_A; ++ww) s += part[ww][tid];
        g_partials[blockIdx.x * NE + tid] = s;
    }
    __threadfence();
    __syncthreads();
    if (tid == 0) isLast = (atomicAdd(&g_counter, 1) == GRID_A - 1);
    __syncthreads();
    if (!isLast) return;

    __threadfence();
    const int e  = tid & 63;
    const int sl = tid >> 6;
    float s = 0.f;
    for (int j = 0; j < GRID_A / 8; ++j)
        s += g_partials[(sl * (GRID_A / 8) + j) * NE + e];
    __syncthreads();
    part[sl][e] = s;
    __syncthreads();
    if (tid < NE) {
        float tot = 0.f;
#pragma unroll
        for (int q = 0; q < 8; ++q) tot += part[q][tid];
        part[8][tid] = __logf(tot * (1.0f / (float)N_TOK));  // log expert_load
    }
    __syncthreads();
    if (tid == 0) {
        float sum = 0.f;
        for (int k = 0; k < NE; ++k) sum += part[8][k];
        // sum_e u*(log u - log load_e), u = 1/64
        out[LOSS_OFF] = -__logf(64.0f) - sum * (1.0f / (float)NE);
        g_counter = 0;
    }
}

// ---------------------------------------------------------------------------
extern "C" void kernel_launch(void* const* d_in, const int* in_sizes, int n_in,
                              void* d_out, int out_size)
{
    const float* x = (const float*)d_in[0];       // (8, 8192, 2048) f32
    const float* w = (const float*)d_in[1];       // (64, 2048) f32
    float* out = (float*)d_out;

    gemm_kernel<<<N_TOK / 128, 128>>>(x, w);
    for (int it = 0; it < N_IT; ++it)
        sinkhorn_step<<<GRID_A, BLOCK_A>>>(it);
    finalize_kernel<<<GRID_A, BLOCK_A>>>(out);
}

// round 9
// speedup vs baseline: 1.2142x; 1.2142x over previous
#include <cuda_runtime.h>

// ---------------------------------------------------------------------------
// OTRouter: logits GEMM -> 20-iter Sinkhorn -> pi, top-8, KL loss
//
// Persistent sinkhorn kernel, but with SEQUENTIAL state updates (la[64] in
// registers, updated in place) so the fp32 rounding sequence matches the
// reference op-for-op -- this keeps top-8 tie decisions correlated with the
// reference (the potential-form variant flipped ~6 indices and failed).
// ---------------------------------------------------------------------------

#define N_TOK   65536
#define NE      64
#define KD      2048
#define N_IT    20

#define DISP_ELEMS (N_TOK * NE)
#define IDX_OFF    DISP_ELEMS
#define LOSS_OFF   (IDX_OFF + N_TOK * 8)

#define PGRID   128
#define PBLOCK  512
#define PX_S    516                       // [e][row] stride (conflict-free)

// ---- persistent device scratch --------------------------------------------
__device__ float    g_state[(size_t)N_TOK * NE];       // logits from GEMM
__device__ float    g_partials[2][PGRID * NE];         // double-buffered col partials
__device__ unsigned g_sync_ctr;                        // grid barrier (reset by GEMM)

// ---- packed f32x2 helpers (sm_103a FFMA2) ---------------------------------
__device__ __forceinline__ unsigned long long fma2(unsigned long long a,
                                                   unsigned long long b,
                                                   unsigned long long c) {
    unsigned long long d;
    asm("fma.rn.f32x2 %0, %1, %2, %3;" : "=l"(d) : "l"(a), "l"(b), "l"(c));
    return d;
}
__device__ __forceinline__ unsigned long long pack2(float a) {
    unsigned long long d; unsigned int u = __float_as_uint(a);
    asm("mov.b64 %0, {%1, %1};" : "=l"(d) : "r"(u));
    return d;
}
__device__ __forceinline__ float2 unpack2(unsigned long long v) {
    unsigned int lo, hi;
    asm("mov.b64 {%0, %1}, %2;" : "=r"(lo), "=r"(hi) : "l"(v));
    return make_float2(__uint_as_float(lo), __uint_as_float(hi));
}

// ---------------------------------------------------------------------------
// GEMM: g_state[n][e] = sum_k x[n][k] * w[e][k]   (fp32, packed f32x2 FMA)
// ---------------------------------------------------------------------------
__global__ void __launch_bounds__(128) gemm_kernel(const float* __restrict__ x,
                                                   const float* __restrict__ w)
{
    if (blockIdx.x == 0 && threadIdx.x == 0) g_sync_ctr = 0;  // barrier reset

    __shared__ __align__(16) float xs[32][132];
    __shared__ __align__(16) float ws[32][68];

    const int tid = threadIdx.x;
    const int tx = tid & 7;
    const int ty = tid >> 3;
    const int rowBase = blockIdx.x * 128;

    unsigned long long acc[8][4];
#pragma unroll
    for (int r = 0; r < 8; ++r)
#pragma unroll
        for (int c = 0; c < 4; ++c) acc[r][c] = 0ULL;

    for (int k0 = 0; k0 < KD; k0 += 32) {
#pragma unroll
        for (int i = 0; i < 8; ++i) {
            int q = tid + i * 128;
            int m = q >> 3, c4 = q & 7;
            float4 f = *(const float4*)(x + (size_t)(rowBase + m) * KD + k0 + c4 * 4);
            xs[c4 * 4 + 0][m] = f.x; xs[c4 * 4 + 1][m] = f.y;
            xs[c4 * 4 + 2][m] = f.z; xs[c4 * 4 + 3][m] = f.w;
        }
#pragma unroll
        for (int i = 0; i < 4; ++i) {
            int q = tid + i * 128;
            int e = q >> 3, c4 = q & 7;
            float4 f = *(const float4*)(w + (size_t)e * KD + k0 + c4 * 4);
            ws[c4 * 4 + 0][e] = f.x; ws[c4 * 4 + 1][e] = f.y;
            ws[c4 * 4 + 2][e] = f.z; ws[c4 * 4 + 3][e] = f.w;
        }
        __syncthreads();

#pragma unroll
        for (int kk = 0; kk < 32; ++kk) {
            float4 a0 = *(const float4*)&xs[kk][ty * 8];
            float4 a1 = *(const float4*)&xs[kk][ty * 8 + 4];
            ulonglong2 wA = *(const ulonglong2*)&ws[kk][tx * 8];
            ulonglong2 wB = *(const ulonglong2*)&ws[kk][tx * 8 + 4];
            float av[8] = {a0.x, a0.y, a0.z, a0.w, a1.x, a1.y, a1.z, a1.w};
#pragma unroll
            for (int r = 0; r < 8; ++r) {
                unsigned long long ap = pack2(av[r]);
                acc[r][0] = fma2(ap, wA.x, acc[r][0]);
                acc[r][1] = fma2(ap, wA.y, acc[r][1]);
                acc[r][2] = fma2(ap, wB.x, acc[r][2]);
                acc[r][3] = fma2(ap, wB.y, acc[r][3]);
            }
        }
        __syncthreads();
    }

#pragma unroll
    for (int r = 0; r < 8; ++r) {
        int gr = rowBase + ty * 8 + r;
        float2 p0 = unpack2(acc[r][0]);
        float2 p1 = unpack2(acc[r][1]);
        float2 p2 = unpack2(acc[r][2]);
        float2 p3 = unpack2(acc[r][3]);
        float* dst = g_state + (size_t)gr * NE + tx * 8;
        *(float4*)dst       = make_float4(p0.x, p0.y, p1.x, p1.y);
        *(float4*)(dst + 4) = make_float4(p2.x, p2.y, p3.x, p3.y);
    }
}

// ---------------------------------------------------------------------------
// Grid-wide barrier (all PGRID blocks co-resident; counter reset by GEMM).
// ---------------------------------------------------------------------------
__device__ __forceinline__ void grid_sync(unsigned goal)
{
    __syncthreads();
    if (threadIdx.x == 0) {
        __threadfence();
        atomicAdd(&g_sync_ctr, 1u);
        while (*((volatile unsigned*)&g_sync_ctr) < goal) __nanosleep(64);
        __threadfence();
    }
    __syncthreads();
}

// ---------------------------------------------------------------------------
// Persistent Sinkhorn: 1 thread = 1 token row (64 floats in registers),
// updated in place each iteration (reference rounding sequence).
// ---------------------------------------------------------------------------
#define SMEM_BYTES (64 * PX_S * 4 + PBLOCK * 4 + 8 * 68 * 4 + 64 * 4)

__global__ void __launch_bounds__(PBLOCK) sinkhorn_persistent(float* __restrict__ out)
{
    extern __shared__ __align__(16) float sm[];
    float* px   = sm;                        // [64][PX_S] transpose scratch
    float* sinv = px + 64 * PX_S;            // [512] 1/rowsum
    float* red  = sinv + PBLOCK;             // [8][68]
    float* cl   = red + 8 * 68;              // [64]  this-iteration colLSE

    const int tid = threadIdx.x;
    const int row = blockIdx.x * PBLOCK + tid;

    if (tid < NE) cl[tid] = 0.f;

    // la = (-logit) / 0.05  (exact division, matching cost/EPSILON)
    float la[64];
    {
        const float4* src = (const float4*)(g_state + (size_t)row * NE);
#pragma unroll
        for (int q = 0; q < 16; ++q) {
            float4 f = src[q];
            la[4 * q + 0] = __fdiv_rn(-f.x, 0.05f);
            la[4 * q + 1] = __fdiv_rn(-f.y, 0.05f);
            la[4 * q + 2] = __fdiv_rn(-f.z, 0.05f);
            la[4 * q + 3] = __fdiv_rn(-f.w, 0.05f);
        }
    }
    __syncthreads();

    for (int it = 0; it < N_IT; ++it) {
        // ---- apply previous iteration's column norm (0 on iter 0) ---------
#pragma unroll
        for (int e = 0; e < 64; e += 4) {
            float4 c4 = *(const float4*)(cl + e);
            la[e]     -= c4.x;
            la[e + 1] -= c4.y;
            la[e + 2] -= c4.z;
            la[e + 3] -= c4.w;
        }

        // ---- row logsumexp (thread-local) ---------------------------------
        float m = -3.4e38f;
#pragma unroll
        for (int e = 0; e < 64; e += 4)
            m = fmaxf(m, fmaxf(fmaxf(la[e], la[e + 1]),
                               fmaxf(la[e + 2], la[e + 3])));

        float s0 = 0.f, s1 = 0.f, s2 = 0.f, s3 = 0.f;
#pragma unroll
        for (int e = 0; e < 64; e += 4) {
            float t0 = __expf(la[e]     - m);
            float t1 = __expf(la[e + 1] - m);
            float t2 = __expf(la[e + 2] - m);
            float t3 = __expf(la[e + 3] - m);
            px[(e    ) * PX_S + tid] = t0;
            px[(e + 1) * PX_S + tid] = t1;
            px[(e + 2) * PX_S + tid] = t2;
            px[(e + 3) * PX_S + tid] = t3;
            s0 += t0; s1 += t1; s2 += t2; s3 += t3;
        }
        float s = (s0 + s1) + (s2 + s3);
        float lse = m + __logf(s);
        sinv[tid] = 1.0f / s;

        // ---- row norm in place (same rounding event as reference) --------
#pragma unroll
        for (int e = 0; e < 64; ++e) la[e] -= lse;
        __syncthreads();

        // ---- column partials: thread (e, chunk) sums 64 rows of t/s ------
        {
            const int e = tid & 63, ch = tid >> 6;
            const float4* tp = (const float4*)(px + e * PX_S + ch * 64);
            const float4* ip = (const float4*)(sinv + ch * 64);
            float a0 = 0.f, a1 = 0.f, a2 = 0.f, a3 = 0.f;
#pragma unroll
            for (int j = 0; j < 16; ++j) {
                float4 t = tp[j]; float4 iv = ip[j];
                a0 += t.x * iv.x; a1 += t.y * iv.y;
                a2 += t.z * iv.z; a3 += t.w * iv.w;
            }
            red[ch * 68 + e] = (a0 + a1) + (a2 + a3);
        }
        __syncthreads();
        if (tid < NE) {
            float bs = 0.f;
#pragma unroll
            for (int k = 0; k < 8; ++k) bs += red[k * 68 + tid];
            g_partials[it & 1][blockIdx.x * NE + tid] = bs;
        }

        grid_sync((unsigned)(it + 1) * PGRID);

        // ---- colLSE: every block reduces all 128x64 partials --------------
        {
            const int e = tid & 63, grp = tid >> 6;
            float a = 0.f;
#pragma unroll
            for (int b = 0; b < 16; ++b)
                a += __ldcg(&g_partials[it & 1][(grp * 16 + b) * NE + e]);
            red[grp * 68 + e] = a;
        }
        __syncthreads();
        if (tid < NE) {
            float tot = 0.f;
#pragma unroll
            for (int k = 0; k < 8; ++k) tot += red[k * 68 + tid];
            cl[tid] = logf(tot);          // precise log: ordering-critical
        }
        __syncthreads();
    }

    // ---- finalize: apply last column norm, pi = exp(la) -------------------
#pragma unroll
    for (int e = 0; e < 64; e += 4) {
        float4 c4 = *(const float4*)(cl + e);
        la[e]     = __expf(la[e]     - c4.x);
        la[e + 1] = __expf(la[e + 1] - c4.y);
        la[e + 2] = __expf(la[e + 2] - c4.z);
        la[e + 3] = __expf(la[e + 3] - c4.w);
    }

    // dispatch
    {
        float4* dst = (float4*)(out + (size_t)row * NE);
#pragma unroll
        for (int q = 0; q < 16; ++q)
            dst[q] = make_float4(la[4 * q], la[4 * q + 1],
                                 la[4 * q + 2], la[4 * q + 3]);
    }
    // stash pi for the load-loss column sums
#pragma unroll
    for (int e = 0; e < 64; ++e) px[e * PX_S + tid] = la[e];

    // top-8 (strict >, ties -> lowest index; destroys la)
    {
        float idxv[8];
#pragma unroll
        for (int k = 0; k < 8; ++k) {
            float bv = -1.f; int bi = 0;
#pragma unroll
            for (int e = 0; e < 64; ++e)
                if (la[e] > bv) { bv = la[e]; bi = e; }
            idxv[k] = (float)bi;
#pragma unroll
            for (int e = 0; e < 64; ++e)
                if (e == bi) la[e] = -1.f;
        }
        float4* idst = (float4*)(out + IDX_OFF + (size_t)row * 8);
        idst[0] = make_float4(idxv[0], idxv[1], idxv[2], idxv[3]);
        idst[1] = make_float4(idxv[4], idxv[5], idxv[6], idxv[7]);
    }
    __syncthreads();

    // ---- load loss: column sums of pi -> block partials -> block 0 --------
    {
        const int e = tid & 63, ch = tid >> 6;
        const float4* tp = (const float4*)(px + e * PX_S + ch * 64);
        float a0 = 0.f, a1 = 0.f, a2 = 0.f, a3 = 0.f;
#pragma unroll
        for (int j = 0; j < 16; ++j) {
            float4 t = tp[j];
            a0 += t.x; a1 += t.y; a2 += t.z; a3 += t.w;
        }
        red[ch * 68 + e] = (a0 + a1) + (a2 + a3);
    }
    __syncthreads();
    if (tid < NE) {
        float bs = 0.f;
#pragma unroll
        for (int k = 0; k < 8; ++k) bs += red[k * 68 + tid];
        g_partials[N_IT & 1][blockIdx.x * NE + tid] = bs;
    }

    grid_sync((unsigned)(N_IT + 1) * PGRID);

    if (blockIdx.x == 0) {
        const int e = tid & 63, grp = tid >> 6;
        float a = 0.f;
#pragma unroll
        for (int b = 0; b < 16; ++b)
            a += __ldcg(&g_partials[N_IT & 1][(grp * 16 + b) * NE + e]);
        red[grp * 68 + e] = a;
        __syncthreads();
        if (tid < NE) {
            float tot = 0.f;
#pragma unroll
            for (int k = 0; k < 8; ++k) tot += red[k * 68 + tid];
            cl[tid] = logf(tot * (1.0f / (float)N_TOK));   // log expert_load
        }
        __syncthreads();
        if (tid == 0) {
            float ssum = 0.f;
            for (int k = 0; k < NE; ++k) ssum += cl[k];
            out[LOSS_OFF] = -logf(64.0f) - ssum * (1.0f / (float)NE);
        }
    }
}

// ---------------------------------------------------------------------------
extern "C" void kernel_launch(void* const* d_in, const int* in_sizes, int n_in,
                              void* d_out, int out_size)
{
    const float* x = (const float*)d_in[0];
    const float* w = (const float*)d_in[1];
    float* out = (float*)d_out;

    cudaFuncSetAttribute(sinkhorn_persistent,
                         cudaFuncAttributeMaxDynamicSharedMemorySize, SMEM_BYTES);

    gemm_kernel<<<N_TOK / 128, 128>>>(x, w);
    sinkhorn_persistent<<<PGRID, PBLOCK, SMEM_BYTES>>>(out);
}